// round 1
// baseline (speedup 1.0000x reference)
#include <cuda_runtime.h>

// Problem constants (fixed by the dataset)
#define NXc   1024          // input features
#define NFc   4096          // output features
#define BITSc 8             // bit planes
#define Gc    128           // NX/8 packed groups

// Scratch for the decoded effective weight W[f][n] (row-major NF x NX, fp32).
// 16 MB static __device__ array (allocation-free rule).
__device__ float g_W[NFc * NXc];

// ---------------------------------------------------------------------------
// Kernel 1: decode packed sign bytes -> effective weight
//   W[f, 8g+j] = sum_k scale[k,f] * (bit(7-j) of binary[k,f,g] ? +1 : -1)
// tid = f*G + g  (g fastest)  -> binary reads coalesced (stride-1 in g),
// W writes are 2x float4 per thread, coalesced along n.
// ---------------------------------------------------------------------------
__global__ void __launch_bounds__(256)
decode_kernel(const int* __restrict__ binary, const float* __restrict__ scale) {
    int tid = blockIdx.x * blockDim.x + threadIdx.x;   // over NF*G = 524288
    int f = tid >> 7;          // / G
    int g = tid & (Gc - 1);    // % G

    float w[8];
#pragma unroll
    for (int j = 0; j < 8; j++) w[j] = 0.0f;

#pragma unroll
    for (int k = 0; k < BITSc; k++) {
        int   b = binary[(k * NFc + f) * Gc + g];
        float s = scale[k * NFc + f];        // broadcast within warp (same f)
#pragma unroll
        for (int j = 0; j < 8; j++) {
            // element j of the group lives in bit (7 - j)
            w[j] += ((b >> (7 - j)) & 1) ? s : -s;
        }
    }

    float4* p = reinterpret_cast<float4*>(&g_W[f * NXc + g * 8]);
    p[0] = make_float4(w[0], w[1], w[2], w[3]);
    p[1] = make_float4(w[4], w[5], w[6], w[7]);
}

// ---------------------------------------------------------------------------
// Kernel 2: fp32 SGEMM  C[m,n] = sum_k A[m,k]*B[n,k] + bias[n]
//   A = x   (M x K, row-major), M = 4096, K = NX = 1024
//   B = g_W (N x K, row-major), N = NF = 4096  (i.e. C = A * B^T)
// 128x128 block tile, BK=16, 8x8 per-thread microtile split as 4+4 fragments
// for conflict-free shared loads. 256 threads.
// ---------------------------------------------------------------------------
#define BM 128
#define BN 128
#define BK 16

__global__ void __launch_bounds__(256)
sgemm_kernel(const float* __restrict__ A,
             const float* __restrict__ bias,
             float* __restrict__ C,
             int M, int N, int K) {
    __shared__ float As[BK][BM];
    __shared__ float Bs[BK][BN];

    const int tid = threadIdx.x;
    const int tx  = tid & 15;   // 0..15 -> column micro-position
    const int ty  = tid >> 4;   // 0..15 -> row micro-position

    const float* Ab = A   + (size_t)blockIdx.y * BM * K;
    const float* Bb = g_W + (size_t)blockIdx.x * BN * K;

    // global->shared load mapping: each thread loads 2x float4 from A and B
    const int lrow = tid >> 2;          // 0..63
    const int lcol = (tid & 3) * 4;     // 0,4,8,12

    float acc[8][8];
#pragma unroll
    for (int i = 0; i < 8; i++)
#pragma unroll
        for (int j = 0; j < 8; j++) acc[i][j] = 0.0f;

    for (int k0 = 0; k0 < K; k0 += BK) {
#pragma unroll
        for (int r = 0; r < 2; r++) {
            int row = lrow + r * 64;
            float4 va = *reinterpret_cast<const float4*>(Ab + (size_t)row * K + k0 + lcol);
            As[lcol + 0][row] = va.x;
            As[lcol + 1][row] = va.y;
            As[lcol + 2][row] = va.z;
            As[lcol + 3][row] = va.w;
            float4 vb = *reinterpret_cast<const float4*>(Bb + (size_t)row * K + k0 + lcol);
            Bs[lcol + 0][row] = vb.x;
            Bs[lcol + 1][row] = vb.y;
            Bs[lcol + 2][row] = vb.z;
            Bs[lcol + 3][row] = vb.w;
        }
        __syncthreads();

#pragma unroll
        for (int k = 0; k < BK; k++) {
            float ar[8], br[8];
            float4 a0 = *reinterpret_cast<const float4*>(&As[k][ty * 4]);
            float4 a1 = *reinterpret_cast<const float4*>(&As[k][64 + ty * 4]);
            float4 b0 = *reinterpret_cast<const float4*>(&Bs[k][tx * 4]);
            float4 b1 = *reinterpret_cast<const float4*>(&Bs[k][64 + tx * 4]);
            ar[0] = a0.x; ar[1] = a0.y; ar[2] = a0.z; ar[3] = a0.w;
            ar[4] = a1.x; ar[5] = a1.y; ar[6] = a1.z; ar[7] = a1.w;
            br[0] = b0.x; br[1] = b0.y; br[2] = b0.z; br[3] = b0.w;
            br[4] = b1.x; br[5] = b1.y; br[6] = b1.z; br[7] = b1.w;
#pragma unroll
            for (int i = 0; i < 8; i++)
#pragma unroll
                for (int j = 0; j < 8; j++)
                    acc[i][j] = fmaf(ar[i], br[j], acc[i][j]);
        }
        __syncthreads();
    }

    // epilogue: add bias, write float4s
    const float4 bv0 = *reinterpret_cast<const float4*>(bias + blockIdx.x * BN + tx * 4);
    const float4 bv1 = *reinterpret_cast<const float4*>(bias + blockIdx.x * BN + 64 + tx * 4);
    float* Cb = C + (size_t)(blockIdx.y * BM) * N + blockIdx.x * BN;

#pragma unroll
    for (int i = 0; i < 8; i++) {
        int m = (i < 4) ? (ty * 4 + i) : (64 + ty * 4 + (i - 4));
        float4 o0, o1;
        o0.x = acc[i][0] + bv0.x;
        o0.y = acc[i][1] + bv0.y;
        o0.z = acc[i][2] + bv0.z;
        o0.w = acc[i][3] + bv0.w;
        o1.x = acc[i][4] + bv1.x;
        o1.y = acc[i][5] + bv1.y;
        o1.z = acc[i][6] + bv1.z;
        o1.w = acc[i][7] + bv1.w;
        *reinterpret_cast<float4*>(Cb + (size_t)m * N + tx * 4)      = o0;
        *reinterpret_cast<float4*>(Cb + (size_t)m * N + 64 + tx * 4) = o1;
    }
}

// ---------------------------------------------------------------------------
// Launch: decode then GEMM (same stream -> ordered; graph-capturable).
// Inputs (metadata order): x (f32, T*NX), binary (i32, 8*NF*G),
//                          scale (f32, 8*NF), bias (f32, NF)
// Output: f32, T*NF
// ---------------------------------------------------------------------------
extern "C" void kernel_launch(void* const* d_in, const int* in_sizes, int n_in,
                              void* d_out, int out_size) {
    const float* x      = (const float*)d_in[0];
    const int*   binary = (const int*)  d_in[1];
    const float* scale  = (const float*)d_in[2];
    const float* bias   = (const float*)d_in[3];
    float*       out    = (float*)d_out;

    const int M = in_sizes[0] / NXc;   // 4096 tokens
    const int N = NFc;                 // 4096
    const int K = NXc;                 // 1024

    decode_kernel<<<(NFc * Gc) / 256, 256>>>(binary, scale);

    dim3 grid(N / BN, M / BM);         // 32 x 32
    sgemm_kernel<<<grid, 256>>>(x, bias, out, M, N, K);
}

// round 3
// speedup vs baseline: 4.0986x; 4.0986x over previous
#include <cuda_runtime.h>
#include <cstdint>

// Problem constants (fixed by the dataset)
#define NXc   1024          // input features (K)
#define NFc   4096          // output features (N)
#define BITSc 8             // bit planes
#define Gc    128           // NX/8 packed groups
#define Mc    4096          // tokens (2*2048)

#define BM 128
#define BN 128
#define BK 32
#define KC (NXc / BK)       // 32 k-chunks
#define STAGES 3

// Tile = 16KB of floats in fragment-major layout:
//   A tile (per m_blk, kc): [mt(8)][ks(4)][lane(32)][4 regs]    = 4096 floats
//   B tile (per n_blk, kc): [nt(16)][ks(4)][lane(32)][2 regs]   = 4096 floats
#define TILE_FLOATS 4096
#define TILE_BYTES  16384

__device__ float g_Xt[(size_t)Mc * NXc];   // [m_blk(32)][kc(32)][TILE]
__device__ float g_Wt[(size_t)NFc * NXc];  // [n_blk(32)][kc(32)][TILE]

// ---------------------------------------------------------------------------
__device__ __forceinline__ uint32_t smem_u32(const void* p) {
    uint32_t a;
    asm("{ .reg .u64 t; cvta.to.shared.u64 t, %1; cvt.u32.u64 %0, t; }" : "=r"(a) : "l"(p));
    return a;
}
__device__ __forceinline__ void cp_async16(uint32_t saddr, const void* gaddr) {
    asm volatile("cp.async.cg.shared.global [%0], [%1], 16;" :: "r"(saddr), "l"(gaddr) : "memory");
}
__device__ __forceinline__ void cp_commit() {
    asm volatile("cp.async.commit_group;" ::: "memory");
}
template <int N>
__device__ __forceinline__ void cp_wait() {
    asm volatile("cp.async.wait_group %0;" :: "n"(N) : "memory");
}
__device__ __forceinline__ float rn_tf32(float x) {
    uint32_t u;
    asm("cvt.rna.tf32.f32 %0, %1;" : "=r"(u) : "f"(x));
    return __uint_as_float(u);
}
__device__ __forceinline__ void mma_tf32(float* d, const uint32_t* a, const uint32_t* b) {
    asm volatile(
        "mma.sync.aligned.m16n8k8.row.col.f32.tf32.tf32.f32 "
        "{%0,%1,%2,%3}, {%4,%5,%6,%7}, {%8,%9}, {%0,%1,%2,%3};"
        : "+f"(d[0]), "+f"(d[1]), "+f"(d[2]), "+f"(d[3])
        : "r"(a[0]), "r"(a[1]), "r"(a[2]), "r"(a[3]), "r"(b[0]), "r"(b[1]));
}

// ---------------------------------------------------------------------------
// Kernel 1: decode packed signs -> W, fragment-major tf32 layout.
// thread = (f, g); writes the 8 weights of its group as 2 float4 (32B contig).
//   B block element (k,n): lane = (n&7)*4 + (k&3), reg = k>>2  (k within 8)
// ---------------------------------------------------------------------------
__global__ void __launch_bounds__(256)
decode_kernel(const int* __restrict__ binary, const float* __restrict__ scale) {
    int tid = blockIdx.x * blockDim.x + threadIdx.x;   // NF*G threads
    int f = tid >> 7;
    int g = tid & (Gc - 1);

    float w[8];
#pragma unroll
    for (int j = 0; j < 8; j++) w[j] = 0.0f;
#pragma unroll
    for (int k = 0; k < BITSc; k++) {
        int   b = binary[(k * NFc + f) * Gc + g];
        float s = scale[k * NFc + f];
#pragma unroll
        for (int j = 0; j < 8; j++)
            w[j] += ((b >> (7 - j)) & 1) ? s : -s;
    }

    int n_blk = f >> 7;            // / BN
    int nt    = (f & 127) >> 3;    // B block row group
    int kc    = g >> 2;            // k-chunk
    int ks    = g & 3;             // 8-k step within chunk

    float* tile = g_Wt + ((size_t)(n_blk * KC + kc)) * TILE_FLOATS;
    float* p = tile + nt * 256 + ks * 64 + (f & 7) * 8;   // [lane0=(f&7)*4][reg]
    // lanes (f&7)*4 + c, c=0..3 hold (w[c], w[c+4])
    *reinterpret_cast<float4*>(p)     = make_float4(rn_tf32(w[0]), rn_tf32(w[4]),
                                                    rn_tf32(w[1]), rn_tf32(w[5]));
    *reinterpret_cast<float4*>(p + 4) = make_float4(rn_tf32(w[2]), rn_tf32(w[6]),
                                                    rn_tf32(w[3]), rn_tf32(w[7]));
}

// ---------------------------------------------------------------------------
// Kernel 2: repack x -> fragment-major tf32 layout.
// thread = (m_blk, kc, mt, ks, lane); writes its own float4 (4 A regs).
//   A block element (row 0..15, k 0..7): lane = (row&7)*4 + (k&3),
//                                        reg  = (row>>3) + 2*(k>>2)
// ---------------------------------------------------------------------------
__global__ void __launch_bounds__(256)
repack_x_kernel(const float* __restrict__ x) {
    int tid = blockIdx.x * blockDim.x + threadIdx.x;   // M*K/4 threads
    int lane = tid & 31;
    int ks   = (tid >> 5) & 3;
    int mt   = (tid >> 7) & 7;
    int kc   = (tid >> 10) & 31;
    int mblk = tid >> 15;

    int row = mt * 16 + (lane >> 2);           // rows (row, row+8)
    int k   = kc * 32 + ks * 8 + (lane & 3);   // cols (k, k+4)

    const float* xr0 = x + (size_t)(mblk * 128 + row) * NXc;
    const float* xr1 = xr0 + 8 * NXc;

    float4 v;
    v.x = rn_tf32(xr0[k]);
    v.y = rn_tf32(xr1[k]);
    v.z = rn_tf32(xr0[k + 4]);
    v.w = rn_tf32(xr1[k + 4]);

    float* tile = g_Xt + ((size_t)(mblk * KC + kc)) * TILE_FLOATS;
    *reinterpret_cast<float4*>(tile + (mt * 4 + ks) * 128 + lane * 4) = v;
}

// ---------------------------------------------------------------------------
// Kernel 3: tf32 mma.sync GEMM   out = x @ W^T + bias
// 256 threads = 8 warps (2 m x 4 n), warp tile 64x32, 3-stage cp.async.
// ---------------------------------------------------------------------------
#define SMEM_TOTAL (STAGES * 2 * TILE_BYTES)   // 96 KB

__global__ void __launch_bounds__(256)
gemm_kernel(const float* __restrict__ bias, float* __restrict__ out) {
    extern __shared__ float smem[];
    float* sA = smem;                          // [STAGES][TILE_FLOATS]
    float* sB = smem + STAGES * TILE_FLOATS;   // [STAGES][TILE_FLOATS]
    const uint32_t sA0 = smem_u32(sA);
    const uint32_t sB0 = smem_u32(sB);

    const int tid  = threadIdx.x;
    const int lane = tid & 31;
    const int wid  = tid >> 5;
    const int wm   = wid >> 2;      // 0..1
    const int wn   = wid & 3;       // 0..3
    const int n_blk = blockIdx.x;
    const int m_blk = blockIdx.y;

    const char* Ag = (const char*)(g_Xt + (size_t)m_blk * KC * TILE_FLOATS);
    const char* Bg = (const char*)(g_Wt + (size_t)n_blk * KC * TILE_FLOATS);

    float acc[4][4][4];
#pragma unroll
    for (int i = 0; i < 4; i++)
#pragma unroll
        for (int j = 0; j < 4; j++)
#pragma unroll
            for (int r = 0; r < 4; r++) acc[i][j][r] = 0.0f;

    // prefetch stages 0..STAGES-2
#pragma unroll
    for (int c = 0; c < STAGES - 1; c++) {
#pragma unroll
        for (int i = 0; i < 4; i++) {
            cp_async16(sA0 + (c * TILE_BYTES) + i * 4096 + tid * 16,
                       Ag + (size_t)c * TILE_BYTES + i * 4096 + tid * 16);
            cp_async16(sB0 + (c * TILE_BYTES) + i * 4096 + tid * 16,
                       Bg + (size_t)c * TILE_BYTES + i * 4096 + tid * 16);
        }
        cp_commit();
    }

    for (int c = 0; c < KC; c++) {
        cp_wait<STAGES - 2>();
        __syncthreads();

        // prefetch chunk c + STAGES - 1 into the stage freed at iter c-1
        int cp = c + STAGES - 1;
        if (cp < KC) {
            int s = cp % STAGES;
#pragma unroll
            for (int i = 0; i < 4; i++) {
                cp_async16(sA0 + s * TILE_BYTES + i * 4096 + tid * 16,
                           Ag + (size_t)cp * TILE_BYTES + i * 4096 + tid * 16);
                cp_async16(sB0 + s * TILE_BYTES + i * 4096 + tid * 16,
                           Bg + (size_t)cp * TILE_BYTES + i * 4096 + tid * 16);
            }
        }
        cp_commit();

        const float* A = sA + (c % STAGES) * TILE_FLOATS;
        const float* B = sB + (c % STAGES) * TILE_FLOATS;

#pragma unroll
        for (int ks = 0; ks < 4; ks++) {
            uint32_t a[4][4], b[4][2];
#pragma unroll
            for (int i = 0; i < 4; i++) {
                int mt = wm * 4 + i;
                const float4 v = *reinterpret_cast<const float4*>(
                    A + (mt * 4 + ks) * 128 + lane * 4);
                a[i][0] = __float_as_uint(v.x);
                a[i][1] = __float_as_uint(v.y);
                a[i][2] = __float_as_uint(v.z);
                a[i][3] = __float_as_uint(v.w);
            }
#pragma unroll
            for (int j = 0; j < 4; j++) {
                int nt = wn * 4 + j;
                const float2 v = *reinterpret_cast<const float2*>(
                    B + nt * 256 + ks * 64 + lane * 2);
                b[j][0] = __float_as_uint(v.x);
                b[j][1] = __float_as_uint(v.y);
            }
#pragma unroll
            for (int i = 0; i < 4; i++)
#pragma unroll
                for (int j = 0; j < 4; j++)
                    mma_tf32(acc[i][j], a[i], b[j]);
        }
        __syncthreads();
    }

    // epilogue: acc regs -> out (+bias).  c0,c1 at (row, col),(row, col+1);
    // c2,c3 at (row+8, col),(row+8, col+1) with row=lane>>2, col=2*(lane&3).
    const int row0 = m_blk * BM + wm * 64 + (lane >> 2);
    const int col0 = n_blk * BN + wn * 32 + (lane & 3) * 2;
#pragma unroll
    for (int j = 0; j < 4; j++) {
        const int n = col0 + j * 8;
        const float2 bv = *reinterpret_cast<const float2*>(bias + n);
#pragma unroll
        for (int i = 0; i < 4; i++) {
            const int m = row0 + i * 16;
            float2 v0, v1;
            v0.x = acc[i][j][0] + bv.x;
            v0.y = acc[i][j][1] + bv.y;
            v1.x = acc[i][j][2] + bv.x;
            v1.y = acc[i][j][3] + bv.y;
            *reinterpret_cast<float2*>(out + (size_t)m * NFc + n)       = v0;
            *reinterpret_cast<float2*>(out + (size_t)(m + 8) * NFc + n) = v1;
        }
    }
}

// ---------------------------------------------------------------------------
// Launch
// ---------------------------------------------------------------------------
extern "C" void kernel_launch(void* const* d_in, const int* in_sizes, int n_in,
                              void* d_out, int out_size) {
    const float* x      = (const float*)d_in[0];
    const int*   binary = (const int*)  d_in[1];
    const float* scale  = (const float*)d_in[2];
    const float* bias   = (const float*)d_in[3];
    float*       out    = (float*)d_out;

    const int M = in_sizes[0] / NXc;   // 4096

    cudaFuncSetAttribute(gemm_kernel,
                         cudaFuncAttributeMaxDynamicSharedMemorySize, SMEM_TOTAL);

    decode_kernel<<<(NFc * Gc) / 256, 256>>>(binary, scale);
    repack_x_kernel<<<(M * NXc / 4) / 256, 256>>>(x);

    dim3 grid(NFc / BN, M / BM);       // 32 x 32
    gemm_kernel<<<grid, 256, SMEM_TOTAL>>>(bias, out);
}

// round 4
// speedup vs baseline: 7.0141x; 1.7114x over previous
#include <cuda_runtime.h>
#include <cuda_fp16.h>
#include <cstdint>

// Problem constants (fixed by the dataset)
#define NXc   1024          // input features (K)
#define NFc   4096          // output features (N)
#define BITSc 8             // bit planes
#define Gc    128           // NX/8 packed groups
#define Mc    4096          // tokens (2*2048)

#define BM 128
#define BN 128
#define BK 64               // k per chunk (4 k-steps of 16)
#define KC (NXc / BK)       // 16 k-chunks
#define STAGES 3

// Tile = 16KB in fragment-major fp16 layout (uint32 = half2):
//   A tile: [mt(8)][ks(4)][lane(32)][4 regs]  = 4096 u32
//   B tile: [nt(16)][ks(4)][lane(32)][2 regs] = 4096 u32
#define TILE_U32   4096
#define TILE_BYTES 16384

__device__ uint32_t g_Xt[(size_t)Mc * NXc / 2];   // [m_blk(32)][kc(16)][TILE]
__device__ uint32_t g_Wt[(size_t)NFc * NXc / 2];  // [n_blk(32)][kc(16)][TILE]

// ---------------------------------------------------------------------------
__device__ __forceinline__ uint32_t smem_u32(const void* p) {
    uint32_t a;
    asm("{ .reg .u64 t; cvta.to.shared.u64 t, %1; cvt.u32.u64 %0, t; }" : "=r"(a) : "l"(p));
    return a;
}
__device__ __forceinline__ void cp_async16(uint32_t saddr, const void* gaddr) {
    asm volatile("cp.async.cg.shared.global [%0], [%1], 16;" :: "r"(saddr), "l"(gaddr) : "memory");
}
__device__ __forceinline__ void cp_commit() {
    asm volatile("cp.async.commit_group;" ::: "memory");
}
template <int N>
__device__ __forceinline__ void cp_wait() {
    asm volatile("cp.async.wait_group %0;" :: "n"(N) : "memory");
}
__device__ __forceinline__ uint32_t pack_h2(float lo, float hi) {
    __half2 h = __floats2half2_rn(lo, hi);   // lo -> low 16 bits
    return *reinterpret_cast<uint32_t*>(&h);
}
__device__ __forceinline__ void mma_f16(float* d, const uint32_t* a, const uint32_t* b) {
    asm volatile(
        "mma.sync.aligned.m16n8k16.row.col.f32.f16.f16.f32 "
        "{%0,%1,%2,%3}, {%4,%5,%6,%7}, {%8,%9}, {%0,%1,%2,%3};"
        : "+f"(d[0]), "+f"(d[1]), "+f"(d[2]), "+f"(d[3])
        : "r"(a[0]), "r"(a[1]), "r"(a[2]), "r"(a[3]), "r"(b[0]), "r"(b[1]));
}

// ---------------------------------------------------------------------------
// Kernel 1: decode packed signs -> W, fragment-major fp16 B layout.
// thread = (f, gp) where gp indexes 16 consecutive k (2 packed bytes);
// this is exactly one k16-step of one B block row -> writes 4 uint2 (32B).
//   B block (k16 x n8) frag: lane = (n%8)*4 + (k%8)/2, reg = k/8, pos = k%2
// ---------------------------------------------------------------------------
__global__ void __launch_bounds__(256)
decode_kernel(const int* __restrict__ binary, const float* __restrict__ scale) {
    int tid = blockIdx.x * blockDim.x + threadIdx.x;   // NF * G/2 threads
    int f  = tid >> 6;
    int gp = tid & 63;

    float w[16];
#pragma unroll
    for (int j = 0; j < 16; j++) w[j] = 0.0f;
#pragma unroll
    for (int k = 0; k < BITSc; k++) {
        const int* brow = binary + (size_t)(k * NFc + f) * Gc + 2 * gp;
        int   b0 = brow[0];
        int   b1 = brow[1];
        float s  = scale[k * NFc + f];
#pragma unroll
        for (int j = 0; j < 8; j++) {
            w[j]     += ((b0 >> (7 - j)) & 1) ? s : -s;
            w[8 + j] += ((b1 >> (7 - j)) & 1) ? s : -s;
        }
    }

    int n_blk = f >> 7;
    int nt    = (f & 127) >> 3;
    int col   = f & 7;
    int kc    = gp >> 2;           // k-chunk (BK=64)
    int ks    = gp & 3;            // k16-step within chunk

    uint32_t* tile = g_Wt + (size_t)(n_blk * KC + kc) * TILE_U32;
    uint32_t* base = tile + ((nt * 4 + ks) * 32 + col * 4) * 2;
#pragma unroll
    for (int c = 0; c < 4; c++) {
        uint2 v;
        v.x = pack_h2(w[2 * c], w[2 * c + 1]);          // reg b0: k' = 2c, 2c+1
        v.y = pack_h2(w[8 + 2 * c], w[9 + 2 * c]);      // reg b1: k' = 8+2c, 9+2c
        *reinterpret_cast<uint2*>(base + c * 2) = v;
    }
}

// ---------------------------------------------------------------------------
// Kernel 2: repack x -> fragment-major fp16 A layout.
// thread writes one lane's 4 A regs (uint4, 16B).
//   A block (16x16) frag: lane = (row%8)*4 + (k%8)/2,
//     a0=(row,k0/k0+1) a1=(row+8,·) a2=(row,k0+8/9) a3=(row+8,k0+8/9)
// ---------------------------------------------------------------------------
__global__ void __launch_bounds__(256)
repack_x_kernel(const float* __restrict__ x) {
    int tid  = blockIdx.x * blockDim.x + threadIdx.x;   // M*K/8 threads
    int lane = tid & 31;
    int ks   = (tid >> 5) & 3;
    int mt   = (tid >> 7) & 7;
    int kc   = (tid >> 10) & (KC - 1);
    int mblk = tid >> 14;

    int row = mblk * BM + mt * 16 + (lane >> 2);
    int k0  = kc * BK + ks * 16 + (lane & 3) * 2;

    const float* r0 = x + (size_t)row * NXc;
    const float* r1 = r0 + 8 * NXc;

    float2 p00 = *reinterpret_cast<const float2*>(r0 + k0);
    float2 p10 = *reinterpret_cast<const float2*>(r1 + k0);
    float2 p01 = *reinterpret_cast<const float2*>(r0 + k0 + 8);
    float2 p11 = *reinterpret_cast<const float2*>(r1 + k0 + 8);

    uint4 v;
    v.x = pack_h2(p00.x, p00.y);   // a0
    v.y = pack_h2(p10.x, p10.y);   // a1
    v.z = pack_h2(p01.x, p01.y);   // a2
    v.w = pack_h2(p11.x, p11.y);   // a3

    uint32_t* tile = g_Xt + (size_t)(mblk * KC + kc) * TILE_U32;
    *reinterpret_cast<uint4*>(tile + ((mt * 4 + ks) * 32 + lane) * 4) = v;
}

// ---------------------------------------------------------------------------
// Kernel 3: fp16 mma.sync GEMM   out = x @ W^T + bias (fp32 accum)
// 256 threads = 8 warps (2 m x 4 n), warp tile 64x32, 3-stage cp.async.
// ---------------------------------------------------------------------------
#define SMEM_TOTAL (STAGES * 2 * TILE_BYTES)   // 96 KB

__global__ void __launch_bounds__(256)
gemm_kernel(const float* __restrict__ bias, float* __restrict__ out) {
    extern __shared__ uint32_t smem[];
    uint32_t* sA = smem;                          // [STAGES][TILE_U32]
    uint32_t* sB = smem + STAGES * TILE_U32;      // [STAGES][TILE_U32]
    const uint32_t sA0 = smem_u32(sA);
    const uint32_t sB0 = smem_u32(sB);

    const int tid  = threadIdx.x;
    const int lane = tid & 31;
    const int wid  = tid >> 5;
    const int wm   = wid >> 2;      // 0..1
    const int wn   = wid & 3;       // 0..3
    const int n_blk = blockIdx.x;
    const int m_blk = blockIdx.y;

    const char* Ag = (const char*)(g_Xt + (size_t)m_blk * KC * TILE_U32);
    const char* Bg = (const char*)(g_Wt + (size_t)n_blk * KC * TILE_U32);

    float acc[4][4][4];
#pragma unroll
    for (int i = 0; i < 4; i++)
#pragma unroll
        for (int j = 0; j < 4; j++)
#pragma unroll
            for (int r = 0; r < 4; r++) acc[i][j][r] = 0.0f;

    // prefetch stages 0..STAGES-2 (4 x 16B per tile per thread)
#pragma unroll
    for (int c = 0; c < STAGES - 1; c++) {
#pragma unroll
        for (int i = 0; i < 4; i++) {
            cp_async16(sA0 + c * TILE_BYTES + i * 4096 + tid * 16,
                       Ag + (size_t)c * TILE_BYTES + i * 4096 + tid * 16);
            cp_async16(sB0 + c * TILE_BYTES + i * 4096 + tid * 16,
                       Bg + (size_t)c * TILE_BYTES + i * 4096 + tid * 16);
        }
        cp_commit();
    }

    for (int c = 0; c < KC; c++) {
        cp_wait<STAGES - 2>();
        __syncthreads();

        int cp = c + STAGES - 1;
        if (cp < KC) {
            int s = cp % STAGES;
#pragma unroll
            for (int i = 0; i < 4; i++) {
                cp_async16(sA0 + s * TILE_BYTES + i * 4096 + tid * 16,
                           Ag + (size_t)cp * TILE_BYTES + i * 4096 + tid * 16);
                cp_async16(sB0 + s * TILE_BYTES + i * 4096 + tid * 16,
                           Bg + (size_t)cp * TILE_BYTES + i * 4096 + tid * 16);
            }
        }
        cp_commit();

        const uint32_t* A = sA + (c % STAGES) * TILE_U32;
        const uint32_t* B = sB + (c % STAGES) * TILE_U32;

#pragma unroll
        for (int ks = 0; ks < 4; ks++) {
            uint32_t a[4][4], b[4][2];
#pragma unroll
            for (int i = 0; i < 4; i++) {
                int mt = wm * 4 + i;
                uint4 v = *reinterpret_cast<const uint4*>(
                    A + ((mt * 4 + ks) * 32 + lane) * 4);
                a[i][0] = v.x; a[i][1] = v.y; a[i][2] = v.z; a[i][3] = v.w;
            }
#pragma unroll
            for (int j = 0; j < 4; j++) {
                int nt = wn * 4 + j;
                uint2 v = *reinterpret_cast<const uint2*>(
                    B + ((nt * 4 + ks) * 32 + lane) * 2);
                b[j][0] = v.x; b[j][1] = v.y;
            }
#pragma unroll
            for (int i = 0; i < 4; i++)
#pragma unroll
                for (int j = 0; j < 4; j++)
                    mma_f16(acc[i][j], a[i], b[j]);
        }
        __syncthreads();
    }

    // epilogue: c0,c1 at (row, col/col+1); c2,c3 at (row+8, ·)
    const int row0 = m_blk * BM + wm * 64 + (lane >> 2);
    const int col0 = n_blk * BN + wn * 32 + (lane & 3) * 2;
#pragma unroll
    for (int j = 0; j < 4; j++) {
        const int n = col0 + j * 8;
        const float2 bv = *reinterpret_cast<const float2*>(bias + n);
#pragma unroll
        for (int i = 0; i < 4; i++) {
            const int m = row0 + i * 16;
            float2 v0, v1;
            v0.x = acc[i][j][0] + bv.x;
            v0.y = acc[i][j][1] + bv.y;
            v1.x = acc[i][j][2] + bv.x;
            v1.y = acc[i][j][3] + bv.y;
            *reinterpret_cast<float2*>(out + (size_t)m * NFc + n)       = v0;
            *reinterpret_cast<float2*>(out + (size_t)(m + 8) * NFc + n) = v1;
        }
    }
}

// ---------------------------------------------------------------------------
// Launch
// ---------------------------------------------------------------------------
extern "C" void kernel_launch(void* const* d_in, const int* in_sizes, int n_in,
                              void* d_out, int out_size) {
    const float* x      = (const float*)d_in[0];
    const int*   binary = (const int*)  d_in[1];
    const float* scale  = (const float*)d_in[2];
    const float* bias   = (const float*)d_in[3];
    float*       out    = (float*)d_out;

    const int M = in_sizes[0] / NXc;   // 4096

    cudaFuncSetAttribute(gemm_kernel,
                         cudaFuncAttributeMaxDynamicSharedMemorySize, SMEM_TOTAL);

    decode_kernel<<<(NFc * (Gc / 2)) / 256, 256>>>(binary, scale);
    repack_x_kernel<<<(M * NXc / 8) / 256, 256>>>(x);

    dim3 grid(NFc / BN, M / BM);       // 32 x 32
    gemm_kernel<<<grid, 256, SMEM_TOTAL>>>(bias, out);
}